// round 16
// baseline (speedup 1.0000x reference)
#include <cuda_runtime.h>
#include <cuda_bf16.h>
#include <math.h>

// ---- scratch (all zero at module load; self-cleaning per call) ----
#define T_BITS 22
#define T_SIZE (1u << T_BITS)               // 4M counters x 4B = 16MB
__device__ unsigned g_T[T_SIZE];
#define L_CAP (1 << 18)                     // conflict list (expect ~27K)
__device__ uint2 g_L[L_CAP];                // (cell, packed)
__device__ int g_nL;
#define H2_BITS 17
#define H2_SIZE (1u << H2_BITS)             // 128K x 8B = 1MB keyed election
#define H2_MASK (H2_SIZE - 1u)
__device__ unsigned long long g_H2[H2_SIZE];
#define MAXP 524288
__device__ uchar4 g_flag4[MAXP / 4];        // per-pair conflict flag

__device__ __forceinline__ unsigned thash(unsigned cell) {
    return (cell * 2654435761u) >> (32 - T_BITS);
}

__device__ __forceinline__ int bucket_of(int pl, int max_path) {
    int bu = (pl < max_path ? pl : max_path) - 1;
    return bu < 0 ? 0 : bu;
}

// A: count touchers per hashed cell. T is L2-hot (re-dirtied by pass C of the
// previous replay, after its big memset). Fire-and-forget RED.ADD.
__global__ void __launch_bounds__(256)
kA_count(const int4* __restrict__ src4, const int4* __restrict__ dst4,
         int n_quads, int n_pairs, int nn) {
    int q = blockIdx.x * blockDim.x + threadIdx.x;
    if (q >= n_quads) return;
    int4 s4 = __ldg(&src4[q]);
    int4 d4 = __ldg(&dst4[q]);
    int sv[4] = {s4.x, s4.y, s4.z, s4.w};
    int dv[4] = {d4.x, d4.y, d4.z, d4.w};
#pragma unroll
    for (int k = 0; k < 4; k++) {
        int i = q * 4 + k;
        if (i < n_pairs) {
            unsigned cell = (unsigned)sv[k] * (unsigned)nn + (unsigned)dv[k];
            atomicAdd(&g_T[thash(cell)], 1u);
        }
    }
}

// B: flag conflicted pairs (counter > 1), push them to the compact list.
// T still L2-hot. Flags written as one uchar4 per quad (coalesced).
__global__ void __launch_bounds__(256)
kB_flag(const int4* __restrict__ src4, const int4* __restrict__ dst4,
        const int4* __restrict__ path_len4,
        int n_quads, int n_pairs, int nn, int max_path) {
    int q = blockIdx.x * blockDim.x + threadIdx.x;
    if (q >= n_quads) return;
    int4 s4 = __ldg(&src4[q]);
    int4 d4 = __ldg(&dst4[q]);
    int4 p4 = __ldg(&path_len4[q]);
    int sv[4] = {s4.x, s4.y, s4.z, s4.w};
    int dv[4] = {d4.x, d4.y, d4.z, d4.w};
    int pv[4] = {p4.x, p4.y, p4.z, p4.w};

    unsigned cell[4], c[4];
    bool act[4];
#pragma unroll
    for (int k = 0; k < 4; k++) {
        int i = q * 4 + k;
        act[k] = (i < n_pairs);
        cell[k] = act[k] ? (unsigned)sv[k] * (unsigned)nn + (unsigned)dv[k] : 0u;
    }
#pragma unroll
    for (int k = 0; k < 4; k++)           // batched L2 reads (MLP)
        c[k] = act[k] ? __ldg(&g_T[thash(cell[k])]) : 0u;

    uchar4 fl = make_uchar4(0, 0, 0, 0);
    unsigned char* flp = &fl.x;
#pragma unroll
    for (int k = 0; k < 4; k++) {
        if (act[k] && c[k] > 1u) {
            flp[k] = 1;
            int i = q * 4 + k;
            unsigned packed = ((unsigned)(i + 1) << 3) |
                              (unsigned)bucket_of(pv[k], max_path);
            int slot = atomicAdd(&g_nL, 1);
            if (slot < L_CAP) g_L[slot] = make_uint2(cell[k], packed);
        }
    }
    g_flag4[q] = fl;
}

// D: election over the tiny conflict list (R7-proven keyed CAS-max).
__global__ void kD_elect(void) {
    int n = min(g_nL, L_CAP);
    for (int s = blockIdx.x * blockDim.x + threadIdx.x; s < n;
         s += gridDim.x * blockDim.x) {
        uint2 e = g_L[s];
        unsigned long long cid  = (unsigned long long)(e.x + 1u);
        unsigned long long mine = (cid << 23) | (unsigned long long)e.y;
        unsigned h = (e.x * 2654435761u) >> (32 - H2_BITS);
        unsigned long long expected = 0ull;
        for (;;) {
            unsigned long long old = atomicCAS(&g_H2[h], expected, mine);
            if (old == expected) break;
            if ((old >> 23) == cid) {
                if (old >= mine) break;
                expected = old;
            } else { h = (h + 1u) & H2_MASK; expected = 0ull; }
        }
    }
}

// C: non-conflicted pairs store their value directly (plain store: no sector
// fetch). Also resets T (fire-and-forget stores -> T stays L2-dirty for the
// NEXT replay's kA). Single toucher per non-flagged cell -> race-free.
__global__ void __launch_bounds__(256)
kC_store(const float* __restrict__ b,
         const int4* __restrict__ src4, const int4* __restrict__ dst4,
         const int4* __restrict__ path_len4,
         int n_quads, int n_pairs, int nn, int max_path,
         float* __restrict__ out_f) {
    int q = blockIdx.x * blockDim.x + threadIdx.x;
    if (q >= n_quads) return;
    int4 s4 = __ldg(&src4[q]);
    int4 d4 = __ldg(&dst4[q]);
    int4 p4 = __ldg(&path_len4[q]);
    uchar4 fl = g_flag4[q];
    int sv[4] = {s4.x, s4.y, s4.z, s4.w};
    int dv[4] = {d4.x, d4.y, d4.z, d4.w};
    int pv[4] = {p4.x, p4.y, p4.z, p4.w};
    const unsigned char* flp = &fl.x;
#pragma unroll
    for (int k = 0; k < 4; k++) {
        int i = q * 4 + k;
        if (i < n_pairs) {
            unsigned cell = (unsigned)sv[k] * (unsigned)nn + (unsigned)dv[k];
            g_T[thash(cell)] = 0u;                     // reset + keep L2-warm
            if (!flp[k])
                out_f[cell] = __ldg(&b[bucket_of(pv[k], max_path)]);
        }
    }
}

// E1: winners of conflicted cells overwrite their cells (deterministic).
__global__ void kE1_resolve(const float* __restrict__ b,
                            float* __restrict__ out_f) {
    int n = min(g_nL, L_CAP);
    for (int s = blockIdx.x * blockDim.x + threadIdx.x; s < n;
         s += gridDim.x * blockDim.x) {
        uint2 e = g_L[s];
        unsigned long long cid = (unsigned long long)(e.x + 1u);
        unsigned h = (e.x * 2654435761u) >> (32 - H2_BITS);
        for (;;) {
            unsigned long long w = g_H2[h];
            if (w == 0ull) break;                       // defensive
            if ((w >> 23) == cid) {
                if ((unsigned)(w & 0x7FFFFFull) == e.y)  // I'm the winner
                    out_f[e.x] = __ldg(&b[e.y & 7u]);
                break;
            }
            h = (h + 1u) & H2_MASK;
        }
    }
}

// E2: zero H2 and nL for the next replay.
__global__ void kE2_clean(void) {
    int t = blockIdx.x * blockDim.x + threadIdx.x;
    for (unsigned s = t; s < H2_SIZE; s += gridDim.x * blockDim.x)
        g_H2[s] = 0ull;
    if (t == 0) g_nL = 0;
}

extern "C" void kernel_launch(void* const* d_in, const int* in_sizes, int n_in,
                              void* d_out, int out_size) {
    const float* b        = (const float*)d_in[1];
    const int*   src      = (const int*)d_in[2];
    const int*   dst      = (const int*)d_in[3];
    const int*   path_len = (const int*)d_in[4];

    int max_path = in_sizes[1];
    int n_pairs  = in_sizes[2];
    int nn = (int)(sqrt((double)out_size) + 0.5);

    const int T = 256;
    int n_quads = (n_pairs + 3) / 4;
    int blocksQ = (n_quads + T - 1) / T;

    // pre-memset (T-table L2-warm window)
    kA_count<<<blocksQ, T>>>((const int4*)src, (const int4*)dst,
                             n_quads, n_pairs, nn);
    kB_flag<<<blocksQ, T>>>((const int4*)src, (const int4*)dst,
                            (const int4*)path_len,
                            n_quads, n_pairs, nn, max_path);
    kD_elect<<<64, 256>>>();

    // mandatory 256MB zero-fill at CE speed
    cudaMemsetAsync(d_out, 0, (size_t)out_size * sizeof(float), 0);

    // post-memset: fetch-free stores + T reset, then conflict resolution
    kC_store<<<blocksQ, T>>>(b, (const int4*)src, (const int4*)dst,
                             (const int4*)path_len,
                             n_quads, n_pairs, nn, max_path, (float*)d_out);
    kE1_resolve<<<64, 256>>>(b, (float*)d_out);
    kE2_clean<<<128, 256>>>();
}

// round 17
// speedup vs baseline: 2.1047x; 2.1047x over previous
#include <cuda_runtime.h>
#include <cuda_bf16.h>
#include <math.h>

// Final consolidated structure (best measured variant of each phase):
//   memset: out = 0 (CE path, 37us — fastest fill)
//   elect:  atomicMax(out_i[cell], packed), packed = (pair+1)<<3 | bucket
//           1 pair/thread, 2048 blocks (R0 config, 13.5us measured)
//   write:  winner (out_i[cell]==packed) overwrites with float b[bucket]
//           2 pairs/thread, batched reads (R14 config, 16.9us measured)
// packed < 2^23 (positive int). Unique winner per cell -> race-free stores.

#define WPT 2

// Election: fire-and-forget REDG.MAX, one pair per thread (max thread count,
// max memory-level parallelism across warps; no return-value stall).
__global__ void __launch_bounds__(256)
se_elect(const int* __restrict__ src,
         const int* __restrict__ dst,
         const int* __restrict__ path_len,
         int n_pairs, int nn, int max_path,
         int* __restrict__ out_i) {
    int i = blockIdx.x * blockDim.x + threadIdx.x;
    if (i >= n_pairs) return;
    int pl = __ldg(&path_len[i]);
    int bu = (pl < max_path ? pl : max_path) - 1;
    if (bu < 0) bu = 0;
    unsigned cell = (unsigned)__ldg(&src[i]) * (unsigned)nn +
                    (unsigned)__ldg(&dst[i]);
    atomicMax(&out_i[cell], ((i + 1) << 3) | bu);   // fire-and-forget
}

// Write: winners convert packed -> float. WPT independent random reads per
// thread issued back-to-back (overlapped round trips), then compares+stores.
// Stores hit the sectors the reads just fetched into L2.
__global__ void __launch_bounds__(256)
se_write(const float* __restrict__ b,
         const int* __restrict__ src,
         const int* __restrict__ dst,
         const int* __restrict__ path_len,
         int n_pairs, int nn, int max_path,
         int* __restrict__ out_i,
         float* __restrict__ out_f) {
    int tid = blockIdx.x * blockDim.x + threadIdx.x;
    int nth = gridDim.x * blockDim.x;

    unsigned cell[WPT];
    int packed[WPT], bu[WPT], w[WPT];
    bool act[WPT];

#pragma unroll
    for (int k = 0; k < WPT; k++) {
        int i = tid + k * nth;
        act[k] = (i < n_pairs);
        if (act[k]) {
            int pl = __ldg(&path_len[i]);
            int t = (pl < max_path ? pl : max_path) - 1;
            bu[k] = t < 0 ? 0 : t;
            packed[k] = ((i + 1) << 3) | bu[k];
            cell[k] = (unsigned)__ldg(&src[i]) * (unsigned)nn +
                      (unsigned)__ldg(&dst[i]);
        }
    }
    // independent random reads in flight together
#pragma unroll
    for (int k = 0; k < WPT; k++)
        if (act[k]) w[k] = __ldcg(&out_i[cell[k]]);
#pragma unroll
    for (int k = 0; k < WPT; k++)
        if (act[k] && w[k] == packed[k])
            out_f[cell[k]] = __ldg(&b[bu[k]]);
}

extern "C" void kernel_launch(void* const* d_in, const int* in_sizes, int n_in,
                              void* d_out, int out_size) {
    // inputs: x [n_nodes,128] f32 (unused), b [max_path] f32,
    //         src [n_pairs] i32, dst [n_pairs] i32, path_len [n_pairs] i32
    const float* b        = (const float*)d_in[1];
    const int*   src      = (const int*)d_in[2];
    const int*   dst      = (const int*)d_in[3];
    const int*   path_len = (const int*)d_in[4];

    int max_path = in_sizes[1];
    int n_pairs  = in_sizes[2];
    int nn = (int)(sqrt((double)out_size) + 0.5);

    int*   out_i = (int*)d_out;
    float* out_f = (float*)d_out;

    const int T = 256;

    // 1) mandatory 256MB zero-fill at CE speed (also zeroes the elect table)
    cudaMemsetAsync(d_out, 0, (size_t)out_size * sizeof(float), 0);

    // 2) election: 1 pair/thread, 2048 blocks (best measured config)
    int blocksA = (n_pairs + T - 1) / T;
    se_elect<<<blocksA, T>>>(src, dst, path_len, n_pairs, nn, max_path, out_i);

    // 3) write: 2 pairs/thread batched reads, 1024 blocks (best measured config)
    int blocksB = (n_pairs + T * WPT - 1) / (T * WPT);
    se_write<<<blocksB, T>>>(b, src, dst, path_len,
                             n_pairs, nn, max_path, out_i, out_f);
}